// round 13
// baseline (speedup 1.0000x reference)
#include <cuda_runtime.h>
#include <math.h>

#define B 128
#define C 1024
#define DIN 1024
#define TWO_D 2048
#define NUM_CLASSES 10
#define ALPHA 1e-3f
#define GAMMA 1e-2f

#define BM 64
#define BN 256
#define BK 32
#define PAD 4
#define KSPLIT 16
#define KSLICE (TWO_D / KSPLIT)   // 128  (aligned: each slice is in one half)
#define NT (KSLICE / BK)          // 4 tiles
#define NCTA 128

#define SA_STRIDE (BM + PAD)              // 68
#define SB_STRIDE (BN + PAD)              // 260
#define SA_BUF (BK * SA_STRIDE)           // 2176 floats
#define SB_BUF (BK * SB_STRIDE)           // 8320 floats
#define SMEM_FLOATS (2 * SA_BUF + 2 * SB_BUF)
#define SMEM_BYTES (SMEM_FLOATS * 4)      // 83968 B

// Scratch (static device globals; no dynamic allocation)
__device__ float g_pmin[B];
__device__ float g_pmax[B];
__device__ float g_sum[C];         // rowsum(T) via REDG
__device__ float g_choice[B][C];   // numerator via REDG
// self-resetting barrier counters (zero-initialized; return to 0 every call)
__device__ unsigned g_bar[4];      // {arrive0, confirm0, arrive1, confirm1}

// Grid-wide barrier: all NCTA CTAs arrive, last confirmer resets both counters.
__device__ __forceinline__ void grid_barrier(unsigned* arrive, unsigned* confirm) {
    __threadfence();            // make this thread's prior writes/atomics visible
    __syncthreads();            // all threads of CTA have fenced
    if (threadIdx.x == 0) {
        atomicAdd(arrive, 1u);
        while (atomicAdd(arrive, 0u) < NCTA) { }
        unsigned o = atomicAdd(confirm, 1u);
        if (o == NCTA - 1) {    // everyone has passed the arrive-spin
            atomicExch(arrive, 0u);
            atomicExch(confirm, 0u);
        }
    }
    __syncthreads();
}

// ---------------------------------------------------------------------------
// Single fused kernel. grid=(4,2,16)=128 CTAs (one wave), 1024 threads.
// Phase 0: zero g_choice row bid + minmax partial of x row bid (+ CTA0: g_sum)
// Phase 1: min-sum GEMM (A normalized on the fly), REDG into g_choice/g_sum
// Phase 2: CTA bid does the per-batch-row argmax / label-sum / one-hot output
// ---------------------------------------------------------------------------
__global__ void __launch_bounds__(1024) k_fused(const float* __restrict__ x,
                                                const float* __restrict__ T,
                                                const int* __restrict__ committed,
                                                const int* __restrict__ labels,
                                                const int* __restrict__ counts,
                                                float* __restrict__ out) {
    extern __shared__ float sm[];
    float* sA = sm;                  // [2][BK][BM+PAD]
    float* sB = sm + 2 * SA_BUF;     // [2][BK][BN+PAD]

    int tid = threadIdx.x;
    int bid = blockIdx.x + 4 * blockIdx.y + 8 * blockIdx.z;  // 0..127 unique

    // ================= Phase 0 =================
    {
        if (tid < 256)
            ((float4*)&g_choice[bid][0])[tid] = make_float4(0.f, 0.f, 0.f, 0.f);
        if (bid == 0 && tid >= 256 && tid < 512)
            ((float4*)g_sum)[tid - 256] = make_float4(0.f, 0.f, 0.f, 0.f);

        // minmax of x row bid: 1024 threads, 1 float each
        float xv = x[(size_t)bid * DIN + tid];
        float mn = xv, mx = xv;
        #pragma unroll
        for (int o = 16; o > 0; o >>= 1) {
            mn = fminf(mn, __shfl_xor_sync(0xffffffffu, mn, o));
            mx = fmaxf(mx, __shfl_xor_sync(0xffffffffu, mx, o));
        }
        __shared__ float pmn[32], pmx[32];
        if ((tid & 31) == 0) { pmn[tid >> 5] = mn; pmx[tid >> 5] = mx; }
        __syncthreads();
        if (tid < 32) {
            mn = pmn[tid]; mx = pmx[tid];
            #pragma unroll
            for (int o = 16; o > 0; o >>= 1) {
                mn = fminf(mn, __shfl_xor_sync(0xffffffffu, mn, o));
                mx = fmaxf(mx, __shfl_xor_sync(0xffffffffu, mx, o));
            }
            if (tid == 0) { g_pmin[bid] = mn; g_pmax[bid] = mx; }
        }
    }
    grid_barrier(&g_bar[0], &g_bar[1]);

    // ================= Phase 1 =================
    int tx = tid & 63;       // n-group -> n0 = tx*4 (BN=256)
    int ty = tid >> 6;       // m-group -> m0 = ty*4 (BM=64)
    int mbase = blockIdx.y * BM;
    int nbase = blockIdx.x * BN;
    int k0 = blockIdx.z * KSLICE;
    bool comp = (k0 >= DIN);
    int xcol = comp ? (k0 - DIN) : k0;
    bool sumDuty = (blockIdx.y == 0);

    // inline global minmax reduce (128 partials -> mnv, sc)
    __shared__ float smn[4], smx[4];
    if (tid < 128) {
        float mn = g_pmin[tid];
        float mx = g_pmax[tid];
        #pragma unroll
        for (int o = 16; o > 0; o >>= 1) {
            mn = fminf(mn, __shfl_xor_sync(0xffffffffu, mn, o));
            mx = fmaxf(mx, __shfl_xor_sync(0xffffffffu, mx, o));
        }
        if ((tid & 31) == 0) { smn[tid >> 5] = mn; smx[tid >> 5] = mx; }
    }
    __syncthreads();
    float mnv = fminf(fminf(smn[0], smn[1]), fminf(smn[2], smn[3]));
    float mxv = fmaxf(fmaxf(smx[0], smx[1]), fmaxf(smx[2], smx[3]));
    float sc = 1.0f / (mxv - mnv + 1e-10f);

    bool hasA = tid < 512;
    int ra = tid >> 3;       // A rows 0..63 (tid<512), B rows 0..127
    int kv = tid & 7;

    const float4* pA  = (const float4*)&x[(size_t)(mbase + (hasA ? ra : 0)) * DIN + xcol + kv * 4];
    const float4* pB0 = (const float4*)&T[(size_t)(nbase + ra) * TWO_D + k0 + kv * 4];
    const float4* pB1 = (const float4*)&T[(size_t)(nbase + ra + 128) * TWO_D + k0 + kv * 4];

    float acc[4][4];
    #pragma unroll
    for (int i = 0; i < 4; i++)
        #pragma unroll
        for (int j = 0; j < 4; j++) acc[i][j] = 0.0f;

    float tsum0 = 0.0f, tsum1 = 0.0f;

    #define XFORM(v) do { \
        v.x = (v.x - mnv) * sc; v.y = (v.y - mnv) * sc; \
        v.z = (v.z - mnv) * sc; v.w = (v.w - mnv) * sc; \
        if (comp) { v.x = 1.0f - v.x; v.y = 1.0f - v.y; \
                    v.z = 1.0f - v.z; v.w = 1.0f - v.w; } \
    } while (0)

    float4 va = make_float4(0.f, 0.f, 0.f, 0.f);
    if (hasA) va = pA[0];
    float4 vb0 = pB0[0], vb1 = pB1[0];
    tsum0 += (vb0.x + vb0.y) + (vb0.z + vb0.w);
    tsum1 += (vb1.x + vb1.y) + (vb1.z + vb1.w);
    {
        int kc = kv * 4;
        if (hasA) {
            XFORM(va);
            float* a = sA + kc * SA_STRIDE;
            a[ra] = va.x; a[SA_STRIDE + ra] = va.y;
            a[2 * SA_STRIDE + ra] = va.z; a[3 * SA_STRIDE + ra] = va.w;
        }
        float* bp = sB + kc * SB_STRIDE;
        bp[ra] = vb0.x; bp[SB_STRIDE + ra] = vb0.y;
        bp[2 * SB_STRIDE + ra] = vb0.z; bp[3 * SB_STRIDE + ra] = vb0.w;
        bp[ra + 128] = vb1.x; bp[SB_STRIDE + ra + 128] = vb1.y;
        bp[2 * SB_STRIDE + ra + 128] = vb1.z; bp[3 * SB_STRIDE + ra + 128] = vb1.w;
    }
    __syncthreads();

    int buf = 0;
    for (int tt = 0; tt < NT; tt++) {
        if (tt + 1 < NT) {
            int o = (tt + 1) * (BK / 4);
            if (hasA) va = pA[o];
            vb0 = pB0[o]; vb1 = pB1[o];
            tsum0 += (vb0.x + vb0.y) + (vb0.z + vb0.w);
            tsum1 += (vb1.x + vb1.y) + (vb1.z + vb1.w);
        }
        const float* cA = sA + buf * SA_BUF + ty * 4;
        const float* cB = sB + buf * SB_BUF + tx * 4;
        #pragma unroll
        for (int k = 0; k < BK; k++) {
            float4 a = *(const float4*)(cA + k * SA_STRIDE);
            float4 bb = *(const float4*)(cB + k * SB_STRIDE);
            float av[4] = {a.x, a.y, a.z, a.w};
            float bv[4] = {bb.x, bb.y, bb.z, bb.w};
            #pragma unroll
            for (int i = 0; i < 4; i++)
                #pragma unroll
                for (int j = 0; j < 4; j++)
                    acc[i][j] += fminf(av[i], bv[j]);
        }
        if (tt + 1 < NT) {
            int nb = buf ^ 1;
            int kc = kv * 4;
            if (hasA) {
                XFORM(va);
                float* a = sA + nb * SA_BUF + kc * SA_STRIDE;
                a[ra] = va.x; a[SA_STRIDE + ra] = va.y;
                a[2 * SA_STRIDE + ra] = va.z; a[3 * SA_STRIDE + ra] = va.w;
            }
            float* bp = sB + nb * SB_BUF + kc * SB_STRIDE;
            bp[ra] = vb0.x; bp[SB_STRIDE + ra] = vb0.y;
            bp[2 * SB_STRIDE + ra] = vb0.z; bp[3 * SB_STRIDE + ra] = vb0.w;
            bp[ra + 128] = vb1.x; bp[SB_STRIDE + ra + 128] = vb1.y;
            bp[2 * SB_STRIDE + ra + 128] = vb1.z; bp[3 * SB_STRIDE + ra + 128] = vb1.w;
            __syncthreads();
            buf = nb;
        }
    }
    #undef XFORM

    if (sumDuty) {
        atomicAdd(&g_sum[nbase + ra], tsum0);
        atomicAdd(&g_sum[nbase + ra + 128], tsum1);
    }

    int b0 = mbase + ty * 4;
    int c0 = nbase + tx * 4;
    #pragma unroll
    for (int i = 0; i < 4; i++)
        #pragma unroll
        for (int j = 0; j < 4; j++)
            atomicAdd(&g_choice[b0 + i][c0 + j], acc[i][j]);

    grid_barrier(&g_bar[2], &g_bar[3]);

    // ================= Phase 2: CTA bid handles batch row bid =================
    __shared__ float sbins[8][NUM_CLASSES];
    __shared__ float bins[NUM_CLASSES];
    __shared__ float wval[8];
    __shared__ int widx[8];

    if (tid < 256) {
        int b = bid;
        int t = tid;
        int lane = t & 31;
        int wid = t >> 5;

        if (lane < NUM_CLASSES) sbins[wid][lane] = 0.0f;
        __syncwarp();
        // all 8 warps initialized their row; need cross-warp visibility
    }
    __syncthreads();
    if (tid < 256) {
        int b = bid;
        int t = tid;
        int lane = t & 31;
        int wid = t >> 5;

        float4 ch = ((const float4*)&g_choice[b][0])[t];
        float4 sn = ((const float4*)g_sum)[t];
        int4 cm = ((const int4*)committed)[t];
        int4 lb = ((const int4*)labels)[t];
        int4 cn = ((const int4*)counts)[t];

        float den[4] = {ALPHA + sn.x + GAMMA * (float)cn.x,
                        ALPHA + sn.y + GAMMA * (float)cn.y,
                        ALPHA + sn.z + GAMMA * (float)cn.z,
                        ALPHA + sn.w + GAMMA * (float)cn.w};
        float v[4] = {ch.x / den[0], ch.y / den[1], ch.z / den[2], ch.w / den[3]};
        int cmv[4] = {cm.x, cm.y, cm.z, cm.w};
        int lbv[4] = {lb.x, lb.y, lb.z, lb.w};

        int c4 = t * 4;
        float best = -INFINITY;
        int bidx = c4;
        #pragma unroll
        for (int j = 0; j < 4; j++) {
            if (cmv[j]) {
                atomicAdd(&sbins[wid][lbv[j]], v[j]);
                if (v[j] > best) { best = v[j]; bidx = c4 + j; }
            }
        }

        #pragma unroll
        for (int o = 16; o > 0; o >>= 1) {
            float ov = __shfl_xor_sync(0xffffffffu, best, o);
            int oi = __shfl_xor_sync(0xffffffffu, bidx, o);
            if (ov > best || (ov == best && oi < bidx)) { best = ov; bidx = oi; }
        }
        if (lane == 0) { wval[wid] = best; widx[wid] = bidx; }
    }
    __syncthreads();
    if (tid < 256) {
        int b = bid;
        int t = tid;
        int lane = t & 31;
        int wid = t >> 5;
        if (wid == 0) {
            float best = (lane < 8) ? wval[lane] : -INFINITY;
            int bidx = (lane < 8) ? widx[lane] : (C + 1);
            #pragma unroll
            for (int o = 16; o > 0; o >>= 1) {
                float ov = __shfl_xor_sync(0xffffffffu, best, o);
                int oi = __shfl_xor_sync(0xffffffffu, bidx, o);
                if (ov > best || (ov == best && oi < bidx)) { best = ov; bidx = oi; }
            }
            if (lane == 0) widx[0] = bidx;
        } else if (wid == 1 && lane < NUM_CLASSES) {
            float s = 0.0f;
            #pragma unroll
            for (int w = 0; w < 8; w++) s += sbins[w][lane];
            bins[lane] = s;
        }
    }
    __syncthreads();
    if (tid < NUM_CLASSES) {
        int pl = labels[widx[0]];
        out[bid * NUM_CLASSES + tid] = (tid == pl) ? bins[tid] : 0.0f;
    }
}

// ---------------------------------------------------------------------------
extern "C" void kernel_launch(void* const* d_in, const int* in_sizes, int n_in,
                              void* d_out, int out_size) {
    const float* x = (const float*)d_in[0];
    const float* T = (const float*)d_in[1];
    const int* committed = (const int*)d_in[2];
    const int* labels = (const int*)d_in[3];
    const int* counts = (const int*)d_in[4];
    float* out = (float*)d_out;

    cudaFuncSetAttribute(k_fused, cudaFuncAttributeMaxDynamicSharedMemorySize,
                         SMEM_BYTES);

    dim3 g(C / BN, B / BM, KSPLIT);   // (4, 2, 16) = 128 CTAs
    k_fused<<<g, 1024, SMEM_BYTES>>>(x, T, committed, labels, counts, out);
}